// round 5
// baseline (speedup 1.0000x reference)
#include <cuda_runtime.h>
#include <mma.h>
#include <cstdint>
#include <cstddef>

using namespace nvcuda;

// ---------------- problem constants ----------------
#define IDIM   36
#define HID    512
#define ED     1024
#define BATCH  2048
#define OUT_ROW (IDIM * ED)      // 36864 floats per batch row

// ---------------- tile config ----------------
#define BM 128                   // batch rows / CTA
#define BN 128                   // d cols / CTA
#define BK 32                    // k per stage
#define KT (HID / BK)            // 16 k-tiles
#define NTHREADS 256
#define HPAD 40                  // A (h) smem row stride (floats)
#define WPAD 136                 // B (W2) smem row stride (floats)

// ---------------- smem layout (float offsets) ----------------
#define SM_W1   0                            // 512
#define SM_B1   512                          // 512
#define SM_B2R  1024                         // 16*WPAD = 2176
#define SM_H    3200                         // 2 * BM*HPAD = 10240
#define SM_W2   13440                        // 2 * BK*WPAD = 8704
#define SMEM_FLOATS 22144
#define SMEM_BYTES  (SMEM_FLOATS * 4)        // 88576

__device__ __forceinline__ float leaky(float h) {
    return fmaxf(h, 0.01f * h);  // exact LeakyReLU(0.01)
}

// ---------------- kernel ----------------
__global__ void __launch_bounds__(NTHREADS, 1)
cembedder_kernel(const float* __restrict__ x,
                 const float* __restrict__ W1,
                 const float* __restrict__ b1,
                 const float* __restrict__ W2,
                 const float* __restrict__ b2,
                 float* __restrict__ out) {
    extern __shared__ float sm[];
    float* W1s = sm + SM_W1;
    float* B1s = sm + SM_B1;
    float* B2R = sm + SM_B2R;
    float* Hs  = sm + SM_H;    // [2][BM][HPAD]
    float* Ws  = sm + SM_W2;   // [2][BK][WPAD]

    const int tid = threadIdx.x;
    const int wid = tid >> 5;

    // grid decode: mb fastest -> consecutive CTAs reuse the same W2 slice via L2
    const int bid = blockIdx.x;
    const int mb  = bid & 15;          // 0..15  batch block
    const int nb  = (bid >> 4) & 7;    // 0..7   d block
    const int br  = bid >> 7;          // 0..35  branch
    const int b0  = mb * BM;
    const int n0  = nb * BN;

    // warp grid 2(M) x 4(N); warp tile 64x32
    const int wm0 = (wid >> 2) * 64;
    const int wn0 = (wid & 3) * 32;

    // ---- stage W1, b1, b2-replicated tile ----
    for (int i = tid; i < HID; i += NTHREADS) {
        W1s[i] = W1[(size_t)br * HID + i];
        B1s[i] = b1[(size_t)br * HID + i];
    }
    for (int i = tid; i < 16 * BN; i += NTHREADS) {
        const int r = i >> 7, c = i & 127;
        B2R[r * WPAD + c] = b2[(size_t)br * ED + n0 + c];
    }

    // ---- producer roles ----
    // h: thread -> (row = tid>>1, k-chunk of 16 at kc)
    const int hrow = tid >> 1;
    const int kc   = (tid & 1) * 16;
    const float xv = x[(size_t)(b0 + hrow) * IDIM + br];
    float* hdst_base = Hs + hrow * HPAD + kc;   // + stage*BM*HPAD

    // W2: thread -> (k-row = tid>>3, 4 float4 chunks at cols (tid&7)*4 + j*32)
    const int gr = tid >> 3;
    const int gc = (tid & 7) * 4;
    const float* w2p = W2 + (size_t)br * HID * ED + (size_t)gr * ED + n0 + gc;
    float* wdst_base = Ws + gr * WPAD + gc;     // + stage*BK*WPAD

    __syncthreads();   // W1s/B1s/B2R visible

    // ---- init accumulators from b2 (16 identical rows in B2R) ----
    wmma::fragment<wmma::accumulator, 16, 16, 8, float> acc[4][2];
    #pragma unroll
    for (int mf = 0; mf < 4; mf++)
        #pragma unroll
        for (int nf = 0; nf < 2; nf++)
            wmma::load_matrix_sync(acc[mf][nf], B2R + wn0 + nf * 16, WPAD, wmma::mem_row_major);

    // ---- produce stage 0 ----
    {
        #pragma unroll
        for (int j = 0; j < 4; j++) {
            float4 v = *(const float4*)(w2p + j * 32);
            float4 c4;
            c4.x = wmma::__float_to_tf32(v.x); c4.y = wmma::__float_to_tf32(v.y);
            c4.z = wmma::__float_to_tf32(v.z); c4.w = wmma::__float_to_tf32(v.w);
            *(float4*)(wdst_base + j * 32) = c4;
        }
        #pragma unroll
        for (int j4 = 0; j4 < 4; j4++) {
            float4 w1v = *(const float4*)(W1s + kc + j4 * 4);
            float4 b1v = *(const float4*)(B1s + kc + j4 * 4);
            float4 h4;
            h4.x = wmma::__float_to_tf32(leaky(fmaf(xv, w1v.x, b1v.x)));
            h4.y = wmma::__float_to_tf32(leaky(fmaf(xv, w1v.y, b1v.y)));
            h4.z = wmma::__float_to_tf32(leaky(fmaf(xv, w1v.z, b1v.z)));
            h4.w = wmma::__float_to_tf32(leaky(fmaf(xv, w1v.w, b1v.w)));
            *(float4*)(hdst_base + j4 * 4) = h4;
        }
    }
    __syncthreads();   // stage 0 visible

    // ---- main loop: 2-stage double buffer ----
    for (int kt = 0; kt < KT; kt++) {
        const int cur = kt & 1;
        const int nxt = cur ^ 1;
        float* Hc = Hs + cur * (BM * HPAD);
        float* Wc = Ws + cur * (BK * WPAD);

        // issue next-stage W2 global loads (overlap with MMA below)
        float4 w2r[4];
        if (kt + 1 < KT) {
            const float* g = w2p + (size_t)(kt + 1) * BK * ED;
            #pragma unroll
            for (int j = 0; j < 4; j++) w2r[j] = *(const float4*)(g + j * 32);
        }

        // MMA on cur
        #pragma unroll
        for (int k0 = 0; k0 < BK; k0 += 8) {
            wmma::fragment<wmma::matrix_a, 16, 16, 8, wmma::precision::tf32, wmma::row_major> af[4];
            wmma::fragment<wmma::matrix_b, 16, 16, 8, wmma::precision::tf32, wmma::row_major> bf[2];
            #pragma unroll
            for (int mf = 0; mf < 4; mf++)
                wmma::load_matrix_sync(af[mf], Hc + (wm0 + mf * 16) * HPAD + k0, HPAD);
            #pragma unroll
            for (int nf = 0; nf < 2; nf++)
                wmma::load_matrix_sync(bf[nf], Wc + k0 * WPAD + wn0 + nf * 16, WPAD);
            #pragma unroll
            for (int mf = 0; mf < 4; mf++)
                #pragma unroll
                for (int nf = 0; nf < 2; nf++)
                    wmma::mma_sync(acc[mf][nf], af[mf], bf[nf], acc[mf][nf]);
        }

        // produce nxt
        if (kt + 1 < KT) {
            float* wd = wdst_base + nxt * (BK * WPAD);
            #pragma unroll
            for (int j = 0; j < 4; j++) {
                float4 c4;
                c4.x = wmma::__float_to_tf32(w2r[j].x); c4.y = wmma::__float_to_tf32(w2r[j].y);
                c4.z = wmma::__float_to_tf32(w2r[j].z); c4.w = wmma::__float_to_tf32(w2r[j].w);
                *(float4*)(wd + j * 32) = c4;
            }
            float* hd = hdst_base + nxt * (BM * HPAD);
            const int kk = (kt + 1) * BK + kc;
            #pragma unroll
            for (int j4 = 0; j4 < 4; j4++) {
                float4 w1v = *(const float4*)(W1s + kk + j4 * 4);
                float4 b1v = *(const float4*)(B1s + kk + j4 * 4);
                float4 h4;
                h4.x = wmma::__float_to_tf32(leaky(fmaf(xv, w1v.x, b1v.x)));
                h4.y = wmma::__float_to_tf32(leaky(fmaf(xv, w1v.y, b1v.y)));
                h4.z = wmma::__float_to_tf32(leaky(fmaf(xv, w1v.z, b1v.z)));
                h4.w = wmma::__float_to_tf32(leaky(fmaf(xv, w1v.w, b1v.w)));
                *(float4*)(hd + j4 * 4) = h4;
            }
        }
        __syncthreads();
    }

    // ---- epilogue: accumulators already include b2 ----
    #pragma unroll
    for (int mf = 0; mf < 4; mf++) {
        float* orow = out + (size_t)(b0 + wm0 + mf * 16) * OUT_ROW + (size_t)br * ED + n0 + wn0;
        #pragma unroll
        for (int nf = 0; nf < 2; nf++)
            wmma::store_matrix_sync(orow + nf * 16, acc[mf][nf], OUT_ROW, wmma::mem_row_major);
    }
}

// ---------------- launch ----------------
extern "C" void kernel_launch(void* const* d_in, const int* in_sizes, int n_in,
                              void* d_out, int out_size) {
    const float* x = nullptr; const float* W1 = nullptr; const float* b1 = nullptr;
    const float* W2 = nullptr; const float* b2 = nullptr;
    for (int i = 0; i < n_in; i++) {
        int sz = in_sizes[i];
        const float* p = (const float*)d_in[i];
        if (sz == BATCH * IDIM) x = p;
        else if (sz == IDIM * HID) { if (!W1) W1 = p; else b1 = p; }
        else if (sz == IDIM * HID * ED) W2 = p;
        else if (sz == IDIM * ED) b2 = p;
    }
    float* out = (float*)d_out;

    cudaFuncSetAttribute(cembedder_kernel, cudaFuncAttributeMaxDynamicSharedMemorySize, SMEM_BYTES);
    dim3 grid(IDIM * 8 * 16);   // 36 branches x 8 d-blocks x 16 batch-blocks = 4608
    cembedder_kernel<<<grid, NTHREADS, SMEM_BYTES>>>(x, W1, b1, W2, b2, out);
}

// round 7
// speedup vs baseline: 3.8632x; 3.8632x over previous
#include <cuda_runtime.h>
#include <cstdint>
#include <cstddef>
#include <math_constants.h>

// ---------------- problem constants ----------------
#define IDIM   36
#define HID    512
#define ED     1024
#define BATCH  2048
#define NJ     (HID + 1)          // 513 intervals
#define OUT_ROW (IDIM * ED)

// ---------------- persistent scratch (device globals, ~152 MB) ----------------
__device__ float g_A[(size_t)IDIM * NJ * ED];   // slope table
__device__ float g_B[(size_t)IDIM * NJ * ED];   // intercept table (b2 folded in)
__device__ float g_st [IDIM * HID];             // sorted thresholds
__device__ float g_sdw[IDIM * HID];             // sorted delta * W1
__device__ float g_sdb[IDIM * HID];             // sorted delta * b1
__device__ int   g_ski[IDIM * HID];             // sorted original k index
__device__ float g_cw0[IDIM * HID];             // base c0 * W1 (by k)
__device__ float g_cb0[IDIM * HID];             // base c0 * b1 (by k)

// ================= K0: thresholds + ranking (36 CTAs x 512) =================
__global__ void __launch_bounds__(HID)
k0_rank(const float* __restrict__ W1, const float* __restrict__ b1) {
    __shared__ float ts[HID];
    const int i = blockIdx.x;
    const int k = threadIdx.x;

    const float w = W1[(size_t)i * HID + k];
    const float b = b1[(size_t)i * HID + k];

    float t, c0, dw, db;
    if (w > 0.0f) {        // h >= 0 for x >= t ; below all: c = 0.01 ; crossing: +0.99
        t = -b / w; c0 = 0.01f; dw = 0.99f * w; db = 0.99f * b;
    } else if (w < 0.0f) { // h >= 0 for x <= t ; below: c = 1 ; crossing: -0.99
        t = -b / w; c0 = 1.0f;  dw = -0.99f * w; db = -0.99f * b;
    } else {               // constant sign, never crosses
        t = CUDART_INF_F; c0 = (b >= 0.0f) ? 1.0f : 0.01f; dw = 0.0f; db = 0.0f;
    }

    g_cw0[i * HID + k] = c0 * w;
    g_cb0[i * HID + k] = c0 * b;

    ts[k] = t;
    __syncthreads();

    // rank by (t, k) lexicographic -> unique permutation
    int rank = 0;
    for (int kk = 0; kk < HID; kk++) {
        const float tk = ts[kk];
        rank += (tk < t) || (tk == t && kk < k);
    }
    g_st [i * HID + rank] = t;
    g_sdw[i * HID + rank] = dw;
    g_sdb[i * HID + rank] = db;
    g_ski[i * HID + rank] = k;
}

// ================= K1: build A/B tables (36*8 CTAs x 128) =================
#define DBLK 128
__global__ void __launch_bounds__(DBLK)
k1_tables(const float* __restrict__ W2, const float* __restrict__ b2) {
    __shared__ float sdw[HID], sdb[HID], scw[HID], scb[HID];
    __shared__ int   ski[HID];

    const int i    = blockIdx.x >> 3;          // branch
    const int dblk = blockIdx.x & 7;           // d block
    const int d    = dblk * DBLK + threadIdx.x;

    for (int r = threadIdx.x; r < HID; r += DBLK) {
        sdw[r] = g_sdw[i * HID + r];
        sdb[r] = g_sdb[i * HID + r];
        ski[r] = g_ski[i * HID + r];
        scw[r] = g_cw0[i * HID + r];
        scb[r] = g_cb0[i * HID + r];
    }
    __syncthreads();

    const float* w2i = W2 + (size_t)i * HID * ED + d;

    // base interval j = 0
    float a = 0.0f;
    float bb = b2[(size_t)i * ED + d];
    #pragma unroll 4
    for (int k = 0; k < HID; k++) {
        const float w2v = w2i[(size_t)k * ED];
        a  = fmaf(scw[k], w2v, a);
        bb = fmaf(scb[k], w2v, bb);
    }

    float* Ai = g_A + ((size_t)i * NJ) * ED + d;
    float* Bi = g_B + ((size_t)i * NJ) * ED + d;
    Ai[0] = a; Bi[0] = bb;

    // prefix chain over sorted thresholds (W2 slice is L2-hot after base pass)
    #pragma unroll 4
    for (int r = 0; r < HID; r++) {
        const float w2v = w2i[(size_t)ski[r] * ED];
        a  = fmaf(sdw[r], w2v, a);
        bb = fmaf(sdb[r], w2v, bb);
        Ai[(size_t)(r + 1) * ED] = a;
        Bi[(size_t)(r + 1) * ED] = bb;
    }
}

// ================= K2: apply (36*2048 CTAs x 256) =================
__global__ void __launch_bounds__(256)
k2_apply(const float* __restrict__ x, float* __restrict__ out) {
    const int i = blockIdx.x >> 11;            // branch (slow) -> L2 reuse of tables
    const int b = blockIdx.x & 2047;           // batch row (fast)

    const float xv = __ldg(x + (size_t)b * IDIM + i);

    // lower_bound: j = #(sorted_t < xv)
    const float* st = g_st + i * HID;
    int lo = 0, hi = HID;
    #pragma unroll
    for (int it = 0; it < 9; it++) {           // ceil(log2(512)) = 9 -> lo==hi
        const int mid = (lo + hi) >> 1;
        if (__ldg(st + mid) < xv) lo = mid + 1; else hi = mid;
    }
    const int j = lo;

    const float4* A4 = (const float4*)(g_A + ((size_t)i * NJ + j) * ED);
    const float4* B4 = (const float4*)(g_B + ((size_t)i * NJ + j) * ED);
    float4* o4 = (float4*)(out + (size_t)b * OUT_ROW + (size_t)i * ED);

    const int t = threadIdx.x;                 // 256 threads x float4 = 1024 floats
    const float4 av = __ldg(A4 + t);
    const float4 bv = __ldg(B4 + t);
    float4 r;
    r.x = fmaf(xv, av.x, bv.x);
    r.y = fmaf(xv, av.y, bv.y);
    r.z = fmaf(xv, av.z, bv.z);
    r.w = fmaf(xv, av.w, bv.w);
    o4[t] = r;
}

// ---------------- launch ----------------
extern "C" void kernel_launch(void* const* d_in, const int* in_sizes, int n_in,
                              void* d_out, int out_size) {
    const float* x = nullptr; const float* W1 = nullptr; const float* b1 = nullptr;
    const float* W2 = nullptr; const float* b2 = nullptr;
    for (int i = 0; i < n_in; i++) {
        int sz = in_sizes[i];
        const float* p = (const float*)d_in[i];
        if (sz == BATCH * IDIM) x = p;
        else if (sz == IDIM * HID) { if (!W1) W1 = p; else b1 = p; }
        else if (sz == IDIM * HID * ED) W2 = p;
        else if (sz == IDIM * ED) b2 = p;
    }
    float* out = (float*)d_out;

    k0_rank  <<<IDIM, HID>>>(W1, b1);
    k1_tables<<<IDIM * 8, DBLK>>>(W2, b2);
    k2_apply <<<IDIM * BATCH, 256>>>(x, out);
}